// round 1
// baseline (speedup 1.0000x reference)
#include <cuda_runtime.h>
#include <cuda_bf16.h>

// GraphSAGE inference, fused.
//   L1: for each (b,n0) pair p (40960): agg1 = mean_{25} embed[neigh1[p,:]],
//       x = [embed[neigh0[p]], agg1] (128), h1[p] = x @ W1        (128 out)
//   L0: per b: agg0 = mean_{10} h1[b,:,:], x = [embed[inputs[b]], agg0] (192),
//       h0 = sigmoid(x @ W0 + b0)                                  (128 out)
//
// Shapes (fixed): B=4096, N0=10, N1=25, D=64, H1=H0=128.

#define B_     4096
#define N0_    10
#define N1_    25
#define D_     64
#define H1_    128
#define PAIRS  (B_ * N0_)     // 40960
#define GQ     4              // pairs per block in L1 (W reuse factor)

// Scratch (device globals: allocation inside kernel_launch is forbidden)
__device__ float              g_h1[(size_t)PAIRS * H1_];          // 21 MB
__device__ unsigned long long g_W1p[64 * 128];    // (k-pair, j) packed f32x2
__device__ unsigned long long g_W0p[96 * 128];    // (k-pair, j) packed f32x2

// ---- packed-fp32 helpers (FFMA2: only reachable via PTX fma.rn.f32x2) ----
__device__ __forceinline__ unsigned long long pack2(float a, float b) {
    unsigned long long r;
    asm("mov.b64 %0, {%1, %2};" : "=l"(r) : "f"(a), "f"(b));
    return r;
}
__device__ __forceinline__ void unpack2(unsigned long long v, float& a, float& b) {
    asm("mov.b64 {%0, %1}, %2;" : "=f"(a), "=f"(b) : "l"(v));
}
__device__ __forceinline__ void ffma2(unsigned long long& d,
                                      unsigned long long a, unsigned long long b) {
    asm("fma.rn.f32x2 %0, %1, %2, %0;" : "+l"(d) : "l"(a), "l"(b));
}

// ---- weight pre-pack: Wp[k2*ncols + j] = {W[(2k2)*ncols + j], W[(2k2+1)*ncols + j]} ----
__global__ void prep_w1(const float* __restrict__ W1) {
    int k2 = blockIdx.x;            // 0..63
    int j  = threadIdx.x;           // 0..127
    g_W1p[k2 * 128 + j] = pack2(W1[(2 * k2) * 128 + j], W1[(2 * k2 + 1) * 128 + j]);
}
__global__ void prep_w0(const float* __restrict__ W0) {
    int k2 = blockIdx.x;            // 0..95
    int j  = threadIdx.x;           // 0..127
    g_W0p[k2 * 128 + j] = pack2(W0[(2 * k2) * 128 + j], W0[(2 * k2 + 1) * 128 + j]);
}

// ---- Level-1: gather + mean(25) + fc1 (no bias, no act). One block = GQ pairs. ----
__global__ void __launch_bounds__(128) sage_l1(
    const int*   __restrict__ neigh0,
    const int*   __restrict__ neigh1,
    const float* __restrict__ embed)
{
    __shared__ __align__(16) float xq[GQ][128];   // [e_n(64) | agg1(64)]
    __shared__ float part[GQ][64];

    const int tid = threadIdx.x;
    const int c   = tid & 63;       // embed column
    const int g   = tid >> 6;       // neighbor-half 0/1
    const int p0  = blockIdx.x * GQ;

    // ---- gather phase: e_n + 25-row mean per pair, split across 2 halves ----
    float accs[GQ];
    #pragma unroll
    for (int q = 0; q < GQ; q++) {
        const int p = p0 + q;
        if (g == 0)
            xq[q][c] = __ldg(embed + (size_t)__ldg(neigh0 + p) * D_ + c);
        const int* nb = neigh1 + (size_t)p * N1_;
        float acc = 0.f;
        #pragma unroll
        for (int i = g; i < N1_; i += 2)          // g=0: 13 rows, g=1: 12 rows
            acc += __ldg(embed + (size_t)__ldg(nb + i) * D_ + c);
        if (g) part[q][c] = acc; else accs[q] = acc;
    }
    __syncthreads();
    if (g == 0) {
        #pragma unroll
        for (int q = 0; q < GQ; q++)
            xq[q][64 + c] = (accs[q] + part[q][c]) * (1.f / (float)N1_);
    }
    __syncthreads();

    // ---- fc1: thread j computes h1[p][j] for all GQ pairs (W loaded once) ----
    unsigned long long acc2[GQ];
    #pragma unroll
    for (int q = 0; q < GQ; q++) acc2[q] = 0ull;   // {0.f, 0.f}

    #pragma unroll 8
    for (int k2 = 0; k2 < 64; k2++) {
        const unsigned long long w = g_W1p[k2 * 128 + tid];   // coalesced LDG.64
        #pragma unroll
        for (int q = 0; q < GQ; q++) {
            const unsigned long long xv =
                *reinterpret_cast<const unsigned long long*>(&xq[q][2 * k2]);
            ffma2(acc2[q], xv, w);
        }
    }
    #pragma unroll
    for (int q = 0; q < GQ; q++) {
        float a, b; unpack2(acc2[q], a, b);
        g_h1[(size_t)(p0 + q) * H1_ + tid] = a + b;
    }
}

// ---- Level-0: mean(10) over h1 + e_v + fc0 + sigmoid. One block per b. ----
__global__ void __launch_bounds__(128) sage_l0(
    const int*   __restrict__ inputs,
    const float* __restrict__ embed,
    const float* __restrict__ b0,
    float*       __restrict__ out)
{
    __shared__ __align__(16) float x[192];        // [e_v(64) | agg0(128)]
    const int b = blockIdx.x;
    const int j = threadIdx.x;

    float s = 0.f;
    const float* h1p = g_h1 + (size_t)b * (N0_ * H1_) + j;
    #pragma unroll
    for (int n = 0; n < N0_; n++) s += h1p[n * H1_];
    x[64 + j] = s * (1.f / (float)N0_);
    if (j < 64)
        x[j] = __ldg(embed + (size_t)__ldg(inputs + b) * D_ + j);
    __syncthreads();

    unsigned long long acc = 0ull;
    #pragma unroll 8
    for (int k2 = 0; k2 < 96; k2++) {
        const unsigned long long w  = g_W0p[k2 * 128 + j];
        const unsigned long long xv =
            *reinterpret_cast<const unsigned long long*>(&x[2 * k2]);
        ffma2(acc, xv, w);
    }
    float a, bb; unpack2(acc, a, bb);
    const float h = a + bb + __ldg(b0 + j);
    out[(size_t)b * 128 + j] = 1.f / (1.f + __expf(-h));
}

extern "C" void kernel_launch(void* const* d_in, const int* in_sizes, int n_in,
                              void* d_out, int out_size)
{
    // Bind inputs by element count (all distinct for this problem):
    //   inputs 4096 | neigh0 40960 | neigh1 1024000 | embed 64000064
    //   W1 16384 | W0 24576 | b0 128
    const int *inputs = nullptr, *neigh0 = nullptr, *neigh1 = nullptr;
    const float *embed = nullptr, *W1 = nullptr, *W0 = nullptr, *b0 = nullptr;
    for (int i = 0; i < n_in; i++) {
        switch (in_sizes[i]) {
            case 4096:     inputs = (const int*)  d_in[i]; break;
            case 40960:    neigh0 = (const int*)  d_in[i]; break;
            case 1024000:  neigh1 = (const int*)  d_in[i]; break;
            case 64000064: embed  = (const float*)d_in[i]; break;
            case 16384:    W1     = (const float*)d_in[i]; break;
            case 24576:    W0     = (const float*)d_in[i]; break;
            case 128:      b0     = (const float*)d_in[i]; break;
        }
    }

    prep_w1<<<64, 128>>>(W1);
    prep_w0<<<96, 128>>>(W0);
    sage_l1<<<PAIRS / GQ, 128>>>(neigh0, neigh1, embed);
    sage_l0<<<B_, 128>>>(inputs, embed, b0, (float*)d_out);
}

// round 3
// speedup vs baseline: 1.0641x; 1.0641x over previous
#include <cuda_runtime.h>
#include <cuda_bf16.h>

// GraphSAGE inference, fused. Shapes fixed: B=4096, N0=10, N1=25, D=64, H=128.
//   L1: per pair p (40960): agg1 = mean_25 embed[neigh1[p,:]],
//       x = [embed[neigh0[p]] | agg1] (128), h1[p] = x @ W1
//   L0: per b: agg0 = mean_10 h1[b,:,:], x = [embed[inputs[b]] | agg0] (192),
//       out = sigmoid(x @ W0 + b0)

#define B_     4096
#define N0_    10
#define N1_    25
#define D_     64
#define H1_    128
#define PAIRS  (B_ * N0_)   // 40960
#define GQ     16           // pairs per block in L1
#define GB     8            // batch rows per block in L0

// Scratch (device globals: runtime allocation is forbidden)
__device__ float g_h1[(size_t)PAIRS * H1_];            // 21 MB
// Weights repacked as (k4, j) ulonglong2: each ULL is a packed f32x2 over the
// K dimension, so one LDG.128 feeds two fma.rn.f32x2.
__device__ ulonglong2 g_W1q[32 * 128];                 // K=128 -> 32 k4 steps
__device__ ulonglong2 g_W0q[48 * 128];                 // K=192 -> 48 k4 steps

// ---- packed-fp32 helpers (FFMA2 only reachable via PTX fma.rn.f32x2) ----
__device__ __forceinline__ unsigned long long pack2(float a, float b) {
    unsigned long long r;
    asm("mov.b64 %0, {%1, %2};" : "=l"(r) : "f"(a), "f"(b));
    return r;
}
__device__ __forceinline__ void unpack2(unsigned long long v, float& a, float& b) {
    asm("mov.b64 {%0, %1}, %2;" : "=f"(a), "=f"(b) : "l"(v));
}
__device__ __forceinline__ void ffma2(unsigned long long& d,
                                      unsigned long long a, unsigned long long b) {
    asm("fma.rn.f32x2 %0, %1, %2, %0;" : "+l"(d) : "l"(a), "l"(b));
}

// ---- weight pre-pack ----
__global__ void prep_w1(const float* __restrict__ W1) {   // W1: [128,128]
    int k4 = blockIdx.x;            // 0..31
    int j  = threadIdx.x;           // 0..127
    ulonglong2 v;
    v.x = pack2(W1[(4 * k4 + 0) * 128 + j], W1[(4 * k4 + 1) * 128 + j]);
    v.y = pack2(W1[(4 * k4 + 2) * 128 + j], W1[(4 * k4 + 3) * 128 + j]);
    g_W1q[k4 * 128 + j] = v;
}
__global__ void prep_w0(const float* __restrict__ W0) {   // W0: [192,128]
    int k4 = blockIdx.x;            // 0..47
    int j  = threadIdx.x;           // 0..127
    ulonglong2 v;
    v.x = pack2(W0[(4 * k4 + 0) * 128 + j], W0[(4 * k4 + 1) * 128 + j]);
    v.y = pack2(W0[(4 * k4 + 2) * 128 + j], W0[(4 * k4 + 3) * 128 + j]);
    g_W0q[k4 * 128 + j] = v;
}

// ---- Level-1: gather + mean(25) + fc1. 256 threads, 16 pairs per block. ----
__global__ void __launch_bounds__(256) sage_l1(
    const int*   __restrict__ neigh0,
    const int*   __restrict__ neigh1,
    const float* __restrict__ embed)
{
    __shared__ int   sn1[GQ * N1_];                  // 400 neighbor ids
    __shared__ int   sn0[GQ];
    __shared__ __align__(16) float xq[GQ][128];      // [e_n(64) | agg1(64)]

    const int t  = threadIdx.x;
    const int p0 = blockIdx.x * GQ;

    // FIX(R3): 400 ids > 256 threads — must stride, not predicate once.
    for (int i = t; i < GQ * N1_; i += 256)
        sn1[i] = neigh1[(size_t)p0 * N1_ + i];
    if (t < GQ)
        sn0[t] = neigh0[p0 + t];
    __syncthreads();

    // ---- gather: thread owns cell (pair, c4); 16 lanes x float4 = one row ----
    {
        const int c4 = t & 15;                       // float4 column slot
        const int pr = t >> 4;                       // pair 0..15 (one per half-warp)
        const float4* eb = (const float4*)embed;

        float4 a = make_float4(0.f, 0.f, 0.f, 0.f);
        #pragma unroll
        for (int i = 0; i < N1_; i++) {
            const int r = sn1[pr * N1_ + i];
            const float4 v = __ldg(eb + (size_t)r * 16 + c4);
            a.x += v.x; a.y += v.y; a.z += v.z; a.w += v.w;
        }
        const float4 en = __ldg(eb + (size_t)sn0[pr] * 16 + c4);
        *(float4*)&xq[pr][4 * c4] = en;
        const float s = 1.f / (float)N1_;
        *(float4*)&xq[pr][64 + 4 * c4] = make_float4(a.x * s, a.y * s, a.z * s, a.w * s);
    }
    __syncthreads();

    // ---- fc1: thread (j, ph) accumulates 8 pairs; W read once per k4 ----
    {
        const int j  = t & 127;
        const int ph = t >> 7;                       // 0/1 -> pairs [0,8) / [8,16)
        unsigned long long acc[8];
        #pragma unroll
        for (int q = 0; q < 8; q++) acc[q] = 0ull;

        #pragma unroll 4
        for (int k4 = 0; k4 < 32; k4++) {
            const ulonglong2 w = g_W1q[k4 * 128 + j];        // LDG.128
            #pragma unroll
            for (int qq = 0; qq < 8; qq++) {
                const ulonglong2 xv =
                    *(const ulonglong2*)&xq[ph * 8 + qq][4 * k4];  // LDS.128 bcast
                ffma2(acc[qq], xv.x, w.x);
                ffma2(acc[qq], xv.y, w.y);
            }
        }
        #pragma unroll
        for (int qq = 0; qq < 8; qq++) {
            float a, b; unpack2(acc[qq], a, b);
            g_h1[(size_t)(p0 + ph * 8 + qq) * H1_ + j] = a + b;
        }
    }
}

// ---- Level-0: mean(10) + fc0 + sigmoid. 128 threads, 8 batch rows/block. ----
__global__ void __launch_bounds__(128) sage_l0(
    const int*   __restrict__ inputs,
    const float* __restrict__ embed,
    const float* __restrict__ b0,
    float*       __restrict__ out)
{
    __shared__ __align__(16) float x[GB][192];       // [e_v(64) | agg0(128)]
    const int j  = threadIdx.x;
    const int bb = blockIdx.x * GB;

    #pragma unroll
    for (int q = 0; q < GB; q++) {
        float s = 0.f;
        const float* h1p = g_h1 + (size_t)(bb + q) * (N0_ * H1_) + j;
        #pragma unroll
        for (int n = 0; n < N0_; n++) s += h1p[n * H1_];
        x[q][64 + j] = s * (1.f / (float)N0_);
    }
    if (j < 64) {
        #pragma unroll
        for (int q = 0; q < GB; q++)
            x[q][j] = __ldg(embed + (size_t)__ldg(inputs + bb + q) * D_ + j);
    }
    __syncthreads();

    unsigned long long acc[GB];
    #pragma unroll
    for (int q = 0; q < GB; q++) acc[q] = 0ull;

    #pragma unroll 4
    for (int k4 = 0; k4 < 48; k4++) {
        const ulonglong2 w = g_W0q[k4 * 128 + j];            // LDG.128
        #pragma unroll
        for (int q = 0; q < GB; q++) {
            const ulonglong2 xv = *(const ulonglong2*)&x[q][4 * k4];  // LDS.128
            ffma2(acc[q], xv.x, w.x);
            ffma2(acc[q], xv.y, w.y);
        }
    }
    const float bj = __ldg(b0 + j);
    #pragma unroll
    for (int q = 0; q < GB; q++) {
        float a, b; unpack2(acc[q], a, b);
        const float h = a + b + bj;
        out[(size_t)(bb + q) * 128 + j] = 1.f / (1.f + __expf(-h));
    }
}

extern "C" void kernel_launch(void* const* d_in, const int* in_sizes, int n_in,
                              void* d_out, int out_size)
{
    // Bind inputs by element count (all distinct):
    //   inputs 4096 | neigh0 40960 | neigh1 1024000 | embed 64000064
    //   W1 16384 | W0 24576 | b0 128
    const int *inputs = nullptr, *neigh0 = nullptr, *neigh1 = nullptr;
    const float *embed = nullptr, *W1 = nullptr, *W0 = nullptr, *b0 = nullptr;
    for (int i = 0; i < n_in; i++) {
        switch (in_sizes[i]) {
            case 4096:     inputs = (const int*)  d_in[i]; break;
            case 40960:    neigh0 = (const int*)  d_in[i]; break;
            case 1024000:  neigh1 = (const int*)  d_in[i]; break;
            case 64000064: embed  = (const float*)d_in[i]; break;
            case 16384:    W1     = (const float*)d_in[i]; break;
            case 24576:    W0     = (const float*)d_in[i]; break;
            case 128:      b0     = (const float*)d_in[i]; break;
        }
    }

    prep_w1<<<32, 128>>>(W1);
    prep_w0<<<48, 128>>>(W0);
    sage_l1<<<PAIRS / GQ, 256>>>(neigh0, neigh1, embed);
    sage_l0<<<B_ / GB, 128>>>(inputs, embed, b0, (float*)d_out);
}